// round 12
// baseline (speedup 1.0000x reference)
#include <cuda_runtime.h>
#include <math.h>

#define B 16
#define LQ 2048
#define EMB1 1024
#define EMB2 768
#define HDIM 1024
#define NHEAD 16
#define DH 64
#define GRIDX 18      // main grid (18,16) = 288 blocks = 144 SMs x 2

// Scratch (static device globals; no allocation in kernel_launch).
__device__ float g_K[B * HDIM];
__device__ float g_V[B * HDIM];
__device__ float g_Weff[B * NHEAD * EMB1];
__device__ float g_c[B * NHEAD];

// Packed f32x2 FMA: acc = a*b + acc elementwise on (lo,hi) float pairs.
__device__ __forceinline__ void fma2(unsigned long long& acc,
                                     unsigned long long a, unsigned long long b) {
    asm("fma.rn.f32x2 %0, %1, %2, %0;" : "+l"(acc) : "l"(a), "l"(b));
}
__device__ __forceinline__ float unpack_sum(unsigned long long a) {
    float lo, hi;
    asm("mov.b64 {%0, %1}, %2;" : "=f"(lo), "=f"(hi) : "l"(a));
    return lo + hi;
}

// ---------------------------------------------------------------------------
// Kernel 1 (proven ~10us): 256 blocks x 512 thr; block stages 4 j-columns of
// both Wk and Wv (24 KB); warp b computes 4 K-dots + 4 V-dots, folded reduce.
// ---------------------------------------------------------------------------
__global__ __launch_bounds__(512, 2) void kv_kernel(const float* __restrict__ emb2,
                          const float* __restrict__ Wk, const float* __restrict__ bk,
                          const float* __restrict__ Wv, const float* __restrict__ bv) {
    __shared__ float4 wk_s[4][EMB2 / 4];   // 12 KB
    __shared__ float4 wv_s[4][EMB2 / 4];   // 12 KB
    int j0 = blockIdx.x * 4;
    int tid = threadIdx.x;

    const float4* Wk4 = (const float4*)(Wk + j0 * EMB2);
    const float4* Wv4 = (const float4*)(Wv + j0 * EMB2);
    for (int t = tid; t < 4 * (EMB2 / 4); t += 512)
        wk_s[t / (EMB2 / 4)][t % (EMB2 / 4)] = __ldg(Wk4 + t);
    for (int t = tid; t < 4 * (EMB2 / 4); t += 512)
        wv_s[t / (EMB2 / 4)][t % (EMB2 / 4)] = __ldg(Wv4 + t);
    __syncthreads();

    int b = tid >> 5, lane = tid & 31;
    const float4* e4 = (const float4*)(emb2 + b * EMB2);

    float4 e[6];
#pragma unroll
    for (int i = 0; i < 6; i++) e[i] = __ldg(&e4[i * 32 + lane]);

    float v[8];                 // v[0..3] = K dots, v[4..7] = V dots
#pragma unroll
    for (int jj = 0; jj < 4; jj++) {
        float ak = 0.f, av = 0.f;
#pragma unroll
        for (int i = 0; i < 6; i++) {
            float4 k = wk_s[jj][i * 32 + lane];
            float4 w = wv_s[jj][i * 32 + lane];
            ak = fmaf(e[i].x, k.x, ak); ak = fmaf(e[i].y, k.y, ak);
            ak = fmaf(e[i].z, k.z, ak); ak = fmaf(e[i].w, k.w, ak);
            av = fmaf(e[i].x, w.x, av); av = fmaf(e[i].y, w.y, av);
            av = fmaf(e[i].z, w.z, av); av = fmaf(e[i].w, w.w, av);
        }
        v[jj] = ak; v[jj + 4] = av;
    }

#pragma unroll
    for (int s = 0; s < 3; s++) {
        int o = 1 << s;
        int bit = (lane >> s) & 1;
#pragma unroll
        for (int j = 0; j < (4 >> s); j++) {
            float keep = bit ? v[2 * j + 1] : v[2 * j];
            float send = bit ? v[2 * j] : v[2 * j + 1];
            v[j] = keep + __shfl_xor_sync(0xffffffffu, send, o);
        }
    }
    v[0] += __shfl_xor_sync(0xffffffffu, v[0], 8);
    v[0] += __shfl_xor_sync(0xffffffffu, v[0], 16);

    if (lane < 4)
        g_K[b * HDIM + j0 + lane] = v[0] + bk[j0 + lane];
    else if (lane < 8)
        g_V[b * HDIM + j0 + lane - 4] = v[0] + bv[j0 + lane - 4];
}

// ---------------------------------------------------------------------------
// Kernel 2: Weff[b,h,e] = sum_d Wq[h*64+d, e] * K[b, h*64+d] (+ c fold).
// ---------------------------------------------------------------------------
__global__ void weff_kernel(const float* __restrict__ Wq, const float* __restrict__ bq) {
    __shared__ float Wq_s[DH * 128];
    __shared__ float Ks[DH];
    int h = blockIdx.y;
    int e0 = blockIdx.x * 128;
    int bg = blockIdx.z;
    int tid = threadIdx.x;

    if (blockIdx.x == 0 && bg == 0 && tid < B) {
        float a = 0.f;
#pragma unroll 16
        for (int d = 0; d < DH; d++)
            a = fmaf(bq[h * DH + d], g_K[tid * HDIM + h * DH + d], a);
        g_c[tid * NHEAD + h] = a;
    }

#pragma unroll 8
    for (int d = 0; d < DH; d++)
        Wq_s[d * 128 + tid] = Wq[(h * DH + d) * EMB1 + e0 + tid];

    for (int bb = 0; bb < 4; bb++) {
        int b = bg * 4 + bb;
        __syncthreads();
        if (tid < DH) Ks[tid] = g_K[b * HDIM + h * DH + tid];
        __syncthreads();
        float a = 0.f;
#pragma unroll 16
        for (int d = 0; d < DH; d++)
            a = fmaf(Wq_s[d * 128 + tid], Ks[d], a);
        g_Weff[(b * NHEAD + h) * EMB1 + e0 + tid] = a;
    }
}

// ---------------------------------------------------------------------------
// Kernel 3 (main, REGISTER-RESIDENT Weff): thread (warp w, lane l) holds
// Weff[h = l&15, e in [w*128 + (l>>4)*64, +64)] = 16 ulonglong2 = 64 regs.
// x is read straight from global (lanes 0-15 / 16-31 share addresses ->
// HW dedup, zero amplification). Main-loop smem traffic ~0: kills the
// L1tex=61.5% bottleneck measured in R11. 4 rows per round; tiny smem
// cross-warp reduce; coalesced stores.
// ---------------------------------------------------------------------------
__global__ __launch_bounds__(256, 2) void main_kernel(const float* __restrict__ emb1,
                                                      float* __restrict__ out) {
    __shared__ float V_s[HDIM];
    __shared__ float c_s[NHEAD];
    __shared__ float part_s[8 * 4 * 17];   // [warp][row][head], padded
    __shared__ float sig_s[4 * NHEAD];

    int b = blockIdx.y;
    int tid = threadIdx.x;
    int warp = tid >> 5, lane = tid & 31;
    int h = lane & 15;
    int ebase = warp * 128 + (lane >> 4) * 64;   // this thread's e-slice start

    // Stage V[b], c[b].
    if (tid < HDIM / 4)
        ((float4*)V_s)[tid] = ((const float4*)(g_V + (size_t)b * HDIM))[tid];
    if (tid < NHEAD) c_s[tid] = g_c[b * NHEAD + tid];

    // Load this thread's Weff slice: 64 floats = 16 ulonglong2 (64 regs).
    ulonglong2 wr[16];
    {
        const ulonglong2* wp =
            (const ulonglong2*)(g_Weff + (size_t)b * NHEAD * EMB1 + h * EMB1 + ebase);
#pragma unroll
        for (int c = 0; c < 16; c++) wr[c] = __ldg(wp + c);
    }
    __syncthreads();

    const float4* Vs4 = (const float4*)V_s;
    float c_h = c_s[h];

    // Rows in rounds of 4: block gx covers r0 = gx*4 + k*(GRIDX*4).
    for (int r0 = blockIdx.x * 4; r0 < LQ; r0 += GRIDX * 4) {
        const ulonglong2* xb =
            (const ulonglong2*)(emb1 + ((size_t)b * LQ + r0) * EMB1) + (ebase >> 2);

        unsigned long long acc[4];
#pragma unroll
        for (int r = 0; r < 4; r++) acc[r] = 0ull;

#pragma unroll
        for (int c = 0; c < 16; c++) {
            ulonglong2 xv[4];
#pragma unroll
            for (int r = 0; r < 4; r++)
                xv[r] = __ldg(xb + r * (EMB1 / 4) + c);
#pragma unroll
            for (int r = 0; r < 4; r++) {
                fma2(acc[r], xv[r].x, wr[c].x);
                fma2(acc[r], xv[r].y, wr[c].y);
            }
        }

        // Combine the two e-halves (lane l <-> l^16 share the same head).
#pragma unroll
        for (int r = 0; r < 4; r++) {
            float p = unpack_sum(acc[r]);
            p += __shfl_xor_sync(0xffffffffu, p, 16);
            if (lane < 16) part_s[(warp * 4 + r) * 17 + h] = p;
        }
        __syncthreads();

        // Cross-warp reduce: 64 threads handle (row, head); sigmoid.
        if (tid < 64) {
            int r = tid >> 4, hh = tid & 15;
            float sum = 0.f;
#pragma unroll
            for (int w = 0; w < 8; w++)
                sum += part_s[(w * 4 + r) * 17 + hh];
            sig_s[r * NHEAD + hh] = __fdividef(1.f, 1.f + __expf(-(sum + c_s[hh])));
        }
        __syncthreads();

        // Store 4 rows: thread t writes float4 index t of each row.
        float4* ob = (float4*)(out + ((size_t)b * LQ + r0) * EMB1);
        int hd = tid >> 4;                 // head of this float4 column
        float4 vv = Vs4[tid];
#pragma unroll
        for (int r = 0; r < 4; r++) {
            float s = sig_s[r * NHEAD + hd];
            float4 o;
            o.x = s * vv.x; o.y = s * vv.y; o.z = s * vv.z; o.w = s * vv.w;
            ob[r * (EMB1 / 4) + tid] = o;
        }
        __syncthreads();   // protect part_s/sig_s before next round
    }
}

// ---------------------------------------------------------------------------
extern "C" void kernel_launch(void* const* d_in, const int* in_sizes, int n_in,
                              void* d_out, int out_size) {
    const float* emb1 = (const float*)d_in[0];
    const float* emb2 = (const float*)d_in[1];
    const float* Wq   = (const float*)d_in[2];
    const float* bq   = (const float*)d_in[3];
    const float* Wk   = (const float*)d_in[4];
    const float* bk   = (const float*)d_in[5];
    const float* Wv   = (const float*)d_in[6];
    const float* bv   = (const float*)d_in[7];
    float* out = (float*)d_out;

    kv_kernel<<<HDIM / 4, 512>>>(emb2, Wk, bk, Wv, bv);
    weff_kernel<<<dim3(EMB1 / 128, NHEAD, 4), 128>>>(Wq, bq);
    main_kernel<<<dim3(GRIDX, B), 256>>>(emb1, out);
}

// round 13
// speedup vs baseline: 1.6384x; 1.6384x over previous
#include <cuda_runtime.h>
#include <math.h>

#define B 16
#define LQ 2048
#define EMB1 1024
#define EMB2 768
#define HDIM 1024
#define NHEAD 16
#define DH 64
#define GRIDX 18      // main grid (18,16) = 288 blocks = 144 SMs x 2
#define PBLK 256      // prologue blocks (co-resident: <= 148*4 at 33KB/512thr)

// Scratch + barrier state (static device globals; no allocation).
__device__ float g_K[B * HDIM];
__device__ float g_V[B * HDIM];
__device__ float g_Weff[B * NHEAD * EMB1];
__device__ float g_c[B * NHEAD];
__device__ unsigned int g_bar = 0;
__device__ unsigned int g_done = 0;

// Packed f32x2 FMA: acc = a*b + acc elementwise on (lo,hi) float pairs.
__device__ __forceinline__ void fma2(unsigned long long& acc,
                                     unsigned long long a, unsigned long long b) {
    asm("fma.rn.f32x2 %0, %1, %2, %0;" : "+l"(acc) : "l"(a), "l"(b));
}
__device__ __forceinline__ float unpack_sum(unsigned long long a) {
    float lo, hi;
    asm("mov.b64 {%0, %1}, %2;" : "=f"(lo), "=f"(hi) : "l"(a));
    return lo + hi;
}

// ---------------------------------------------------------------------------
// Fused prologue: phase A = exact R6 kv body (256 blocks x 512 thr, proven
// ~10us). Grid barrier. Phase B = weff on blocks 0..127: block (h = bid>>3,
// ec = bid&7) stages Wq[h, :, ec*128..+128) (32 KB) once, then computes all
// 16 batches with 4-way batch parallelism across the 512 threads. c fold on
// the ec==0 blocks. Barrier counters reset by the last finishing block.
// ---------------------------------------------------------------------------
__global__ __launch_bounds__(512, 2) void prologue_kernel(
        const float* __restrict__ emb2,
        const float* __restrict__ Wq,   const float* __restrict__ bq,
        const float* __restrict__ Wk,   const float* __restrict__ bk,
        const float* __restrict__ Wv,   const float* __restrict__ bv) {
    extern __shared__ float smx[];
    int bid = blockIdx.x;
    int tid = threadIdx.x;

    // ========================= Phase A: K/V =========================
    {
        float4* wk_s = (float4*)smx;                 // 4*192 float4 = 12 KB
        float4* wv_s = wk_s + 4 * (EMB2 / 4);        // 12 KB
        int j0 = bid * 4;

        const float4* Wk4 = (const float4*)(Wk + j0 * EMB2);
        const float4* Wv4 = (const float4*)(Wv + j0 * EMB2);
        for (int t = tid; t < 4 * (EMB2 / 4); t += 512) wk_s[t] = __ldg(Wk4 + t);
        for (int t = tid; t < 4 * (EMB2 / 4); t += 512) wv_s[t] = __ldg(Wv4 + t);
        __syncthreads();

        int b = tid >> 5, lane = tid & 31;
        const float4* e4 = (const float4*)(emb2 + b * EMB2);

        float4 e[6];
#pragma unroll
        for (int i = 0; i < 6; i++) e[i] = __ldg(&e4[i * 32 + lane]);

        float v[8];                 // v[0..3] = K dots, v[4..7] = V dots
#pragma unroll
        for (int jj = 0; jj < 4; jj++) {
            float ak = 0.f, av = 0.f;
#pragma unroll
            for (int i = 0; i < 6; i++) {
                float4 k = wk_s[jj * (EMB2 / 4) + i * 32 + lane];
                float4 w = wv_s[jj * (EMB2 / 4) + i * 32 + lane];
                ak = fmaf(e[i].x, k.x, ak); ak = fmaf(e[i].y, k.y, ak);
                ak = fmaf(e[i].z, k.z, ak); ak = fmaf(e[i].w, k.w, ak);
                av = fmaf(e[i].x, w.x, av); av = fmaf(e[i].y, w.y, av);
                av = fmaf(e[i].z, w.z, av); av = fmaf(e[i].w, w.w, av);
            }
            v[jj] = ak; v[jj + 4] = av;
        }
#pragma unroll
        for (int s = 0; s < 3; s++) {
            int o = 1 << s;
            int bit = (lane >> s) & 1;
#pragma unroll
            for (int j = 0; j < (4 >> s); j++) {
                float keep = bit ? v[2 * j + 1] : v[2 * j];
                float send = bit ? v[2 * j] : v[2 * j + 1];
                v[j] = keep + __shfl_xor_sync(0xffffffffu, send, o);
            }
        }
        v[0] += __shfl_xor_sync(0xffffffffu, v[0], 8);
        v[0] += __shfl_xor_sync(0xffffffffu, v[0], 16);

        if (lane < 4)
            g_K[b * HDIM + j0 + lane] = v[0] + bk[j0 + lane];
        else if (lane < 8)
            g_V[b * HDIM + j0 + lane - 4] = v[0] + bv[j0 + lane - 4];
    }

    // ===================== Grid barrier (256 blocks) =====================
    __syncthreads();
    if (tid == 0) {
        __threadfence();
        atomicAdd(&g_bar, 1u);
        while (atomicAdd(&g_bar, 0u) < PBLK) { }
    }
    __syncthreads();

    // ========================= Phase B: Weff =========================
    if (bid < 128) {
        float* Wq_s = smx;                 // DH*128 = 8192 floats = 32 KB
        float* Ks = smx + DH * 128;        // 4*64 floats
        int h = bid >> 3;                  // 0..15
        int ec = bid & 7;                  // 0..7
        int e0 = ec * 128;

        // c fold: one block per head (ec==0), threads 0..15 = batches.
        if (ec == 0 && tid < B) {
            float a = 0.f;
#pragma unroll 16
            for (int d = 0; d < DH; d++)
                a = fmaf(bq[h * DH + d], __ldcg(&g_K[tid * HDIM + h * DH + d]), a);
            g_c[tid * NHEAD + h] = a;
        }

        // Stage Wq[h, 0..63, e0..e0+128): each thread 16 floats.
        for (int t = tid; t < DH * 128; t += 512) {
            int d = t >> 7, el = t & 127;
            Wq_s[d * 128 + el] = __ldg(&Wq[(h * DH + d) * EMB1 + e0 + el]);
        }

        int el = tid & 127;        // e within chunk
        int bsub = tid >> 7;       // 0..3: batch sub-index
#pragma unroll
        for (int bg = 0; bg < 4; bg++) {
            __syncthreads();
            if (tid < 4 * DH) {
                int bb = tid >> 6, d = tid & 63;
                Ks[bb * DH + d] = __ldcg(&g_K[(bg * 4 + bb) * HDIM + h * DH + d]);
            }
            __syncthreads();
            int b = bg * 4 + bsub;
            float a = 0.f;
#pragma unroll 16
            for (int d = 0; d < DH; d++)
                a = fmaf(Wq_s[d * 128 + el], Ks[bsub * DH + d], a);
            g_Weff[(b * NHEAD + h) * EMB1 + e0 + el] = a;
        }
    }

    // ================== Reset barrier counters (replay-safe) =============
    __syncthreads();
    if (tid == 0) {
        __threadfence();
        unsigned int d = atomicAdd(&g_done, 1u);
        if (d == PBLK - 1) {       // last block: all others passed the spin
            atomicExch(&g_bar, 0u);
            atomicExch(&g_done, 0u);
        }
    }
}

// ---------------------------------------------------------------------------
// Main kernel: byte-exact R5 row-pair structure (best measured: 80.35 total).
// ---------------------------------------------------------------------------
__global__ __launch_bounds__(256, 2) void main_kernel(const float* __restrict__ emb1,
                                                      float* __restrict__ out) {
    extern __shared__ float sm[];
    float* Weff_s = sm;                    // 16384 floats
    float* V_s = sm + NHEAD * EMB1;        // 1024 floats
    float* c_s = V_s + HDIM;               // 16 floats

    int b = blockIdx.y;
    int tid = threadIdx.x;

    {
        const float4* Wg = (const float4*)(g_Weff + (size_t)b * NHEAD * EMB1);
        float4* Ws4 = (float4*)Weff_s;
#pragma unroll
        for (int i = 0; i < NHEAD * EMB1 / 4 / 256; i++)
            Ws4[i * 256 + tid] = Wg[i * 256 + tid];
        const float4* Vg = (const float4*)(g_V + (size_t)b * HDIM);
        if (tid < HDIM / 4) ((float4*)V_s)[tid] = Vg[tid];
        if (tid < NHEAD) c_s[tid] = g_c[b * NHEAD + tid];
    }
    __syncthreads();

    int warp = tid >> 5, lane = tid & 31;
    const ulonglong2* Wsd = (const ulonglong2*)Weff_s;
    const float4* Vs4 = (const float4*)V_s;
    int hi = lane >> 4;
    float c_l = c_s[lane & 15];

    for (int p = blockIdx.x * 8 + warp; p < LQ / 2; p += GRIDX * 8) {
        const ulonglong2* x0p = (const ulonglong2*)(emb1 + ((size_t)b * LQ + 2 * p) * EMB1);
        const ulonglong2* x1p = x0p + EMB1 / 4;

        ulonglong2 x0 = __ldg(x0p + lane);
        ulonglong2 x1 = __ldg(x1p + lane);

        unsigned long long acc0[NHEAD], acc1[NHEAD];
#pragma unroll
        for (int h = 0; h < NHEAD; h++) { acc0[h] = 0ull; acc1[h] = 0ull; }

#pragma unroll
        for (int i = 0; i < 8; i++) {
            ulonglong2 x0n, x1n;
            if (i < 7) {
                x0n = __ldg(x0p + (i + 1) * 32 + lane);
                x1n = __ldg(x1p + (i + 1) * 32 + lane);
            }
#pragma unroll
            for (int h = 0; h < NHEAD; h++) {
                ulonglong2 w = Wsd[h * 256 + i * 32 + lane];
                fma2(acc0[h], x0.x, w.x);
                fma2(acc0[h], x0.y, w.y);
                fma2(acc1[h], x1.x, w.x);
                fma2(acc1[h], x1.y, w.y);
            }
            if (i < 7) { x0 = x0n; x1 = x1n; }
        }

        float v0[NHEAD], v1[NHEAD];
#pragma unroll
        for (int h = 0; h < NHEAD; h++) {
            v0[h] = unpack_sum(acc0[h]);
            v1[h] = unpack_sum(acc1[h]);
        }
#pragma unroll
        for (int s = 0; s < 4; s++) {
            int o = 1 << s;
            int bit = (lane >> s) & 1;
#pragma unroll
            for (int j = 0; j < (8 >> s); j++) {
                float k0 = bit ? v0[2 * j + 1] : v0[2 * j];
                float s0 = bit ? v0[2 * j] : v0[2 * j + 1];
                v0[j] = k0 + __shfl_xor_sync(0xffffffffu, s0, o);
                float k1 = bit ? v1[2 * j + 1] : v1[2 * j];
                float s1 = bit ? v1[2 * j] : v1[2 * j + 1];
                v1[j] = k1 + __shfl_xor_sync(0xffffffffu, s1, o);
            }
        }
        v0[0] += __shfl_xor_sync(0xffffffffu, v0[0], 16);
        v1[0] += __shfl_xor_sync(0xffffffffu, v1[0], 16);

        float sig0 = __fdividef(1.f, 1.f + __expf(-(v0[0] + c_l)));
        float sig1 = __fdividef(1.f, 1.f + __expf(-(v1[0] + c_l)));

        float4* o0 = (float4*)(out + ((size_t)b * LQ + 2 * p) * EMB1);
        float4* o1 = o0 + EMB1 / 4;
#pragma unroll
        for (int i = 0; i < 8; i++) {
            float s0 = __shfl_sync(0xffffffffu, sig0, 2 * i + hi);
            float s1 = __shfl_sync(0xffffffffu, sig1, 2 * i + hi);
            float4 v = Vs4[i * 32 + lane];
            float4 r0, r1;
            r0.x = s0 * v.x; r0.y = s0 * v.y; r0.z = s0 * v.z; r0.w = s0 * v.w;
            r1.x = s1 * v.x; r1.y = s1 * v.y; r1.z = s1 * v.z; r1.w = s1 * v.w;
            o0[i * 32 + lane] = r0;
            o1[i * 32 + lane] = r1;
        }
    }
}

// ---------------------------------------------------------------------------
extern "C" void kernel_launch(void* const* d_in, const int* in_sizes, int n_in,
                              void* d_out, int out_size) {
    const float* emb1 = (const float*)d_in[0];
    const float* emb2 = (const float*)d_in[1];
    const float* Wq   = (const float*)d_in[2];
    const float* bq   = (const float*)d_in[3];
    const float* Wk   = (const float*)d_in[4];
    const float* bk   = (const float*)d_in[5];
    const float* Wv   = (const float*)d_in[6];
    const float* bv   = (const float*)d_in[7];
    float* out = (float*)d_out;

    int psmem = (DH * 128 + 4 * DH + 32) * (int)sizeof(float);      // ~33 KB
    int msmem = (NHEAD * EMB1 + HDIM + NHEAD) * (int)sizeof(float); // ~69.7 KB
    static bool attr_set = false;
    if (!attr_set) {
        cudaFuncSetAttribute(prologue_kernel, cudaFuncAttributeMaxDynamicSharedMemorySize, psmem);
        cudaFuncSetAttribute(main_kernel, cudaFuncAttributeMaxDynamicSharedMemorySize, msmem);
        attr_set = true;
    }

    prologue_kernel<<<PBLK, 512, psmem>>>(emb2, Wq, bq, Wk, bk, Wv, bv);
    main_kernel<<<dim3(GRIDX, B), 256, msmem>>>(emb1, out);
}